// round 1
// baseline (speedup 1.0000x reference)
#include <cuda_runtime.h>
#include <cstdint>

#define TT 2048
#define BB 512
#define KK 8
#define DD 32
#define DT_F 0.05f
#define SQDT_F 0.22360679774997896f  /* sqrt(0.05) */

// Scratch for 1/sum_k(w) per (t, b). Static __device__ array (no allocs allowed).
__device__ float g_rws[TT * BB];

// ---------- f32x2 helpers (FFMA2 is PTX-only on sm_103a) ----------
__device__ __forceinline__ unsigned long long add2(unsigned long long a, unsigned long long b) {
    unsigned long long d;
    asm("add.rn.f32x2 %0, %1, %2;" : "=l"(d) : "l"(a), "l"(b));
    return d;
}
__device__ __forceinline__ void ffma2(unsigned long long& d, unsigned long long a, unsigned long long b) {
    asm("fma.rn.f32x2 %0, %1, %2, %3;" : "=l"(d) : "l"(a), "l"(b), "l"(d));
}
__device__ __forceinline__ float hsum2(unsigned long long v) {
    float lo, hi;
    asm("mov.b64 {%0, %1}, %2;" : "=f"(lo), "=f"(hi) : "l"(v));
    return lo + hi;
}
__device__ __forceinline__ void unpack2(unsigned long long v, float& lo, float& hi) {
    asm("mov.b64 {%0, %1}, %2;" : "=f"(lo), "=f"(hi) : "l"(v));
}

// ---------- Kernel 1: rws[t*B+b] = 1 / sum_k s_probs[t][b][k] ----------
__global__ void __launch_bounds__(256) rws_kernel(const float* __restrict__ s_probs) {
    int idx = blockIdx.x * blockDim.x + threadIdx.x;  // idx in [0, T*B)
    if (idx < TT * BB) {
        const float4* p = (const float4*)(s_probs + (size_t)idx * KK);
        float4 a = p[0];
        float4 b = p[1];
        float s = ((a.x + a.y) + (a.z + a.w)) + ((b.x + b.y) + (b.z + b.w));
        g_rws[idx] = 1.0f / s;
    }
}

// ---------- Kernel 2: sequential Euler-Maruyama, one CTA per batch ----------
// Thread t of CTA b owns rows (k = t&7, i0 = t>>3) and (k, i0+16) of A_k,
// entirely in registers as f32x2 pairs. z lives in smem (double buffered).
__global__ void __launch_bounds__(128, 4) sde_main(
    const float* __restrict__ z0,
    const float* __restrict__ s_probs,
    const float* __restrict__ noise,
    const float* __restrict__ A_s,
    const float* __restrict__ b_s,
    const float* __restrict__ Q_chol,
    float* __restrict__ ys)
{
    const int b  = blockIdx.x;
    const int t  = threadIdx.x;
    const int k  = t & 7;
    const int ih = t >> 3;        // 0..15
    const int i0 = ih;
    const int i1 = ih + 16;

    __shared__ __align__(16) float  zbuf[2][DD];
    __shared__ __align__(16) float2 pbuf[DD][10];   // [i][k] in first 8, 2 pad (bank-conflict pad)

    // ---- load A rows into registers as f32x2 pairs ----
    unsigned long long A0[16], A1[16];
    {
        const ulonglong2* r0 = (const ulonglong2*)(A_s + (size_t)(k * DD + i0) * DD);
        const ulonglong2* r1 = (const ulonglong2*)(A_s + (size_t)(k * DD + i1) * DD);
#pragma unroll
        for (int q = 0; q < 8; q++) {
            ulonglong2 v0 = r0[q]; A0[2 * q] = v0.x; A0[2 * q + 1] = v0.y;
            ulonglong2 v1 = r1[q]; A1[2 * q] = v1.x; A1[2 * q + 1] = v1.y;
        }
    }
    const float dtb0 = DT_F * b_s[k * DD + i0];
    const float dtb1 = DT_F * b_s[k * DD + i1];
    const float qc0  = Q_chol[k * DD + i0];
    const float qc1  = Q_chol[k * DD + i1];

    // ---- init z ----
    float zreg = 0.0f;
    if (t < DD) {
        zreg = z0[b * DD + t];
        zbuf[0][t] = zreg;
    }

    // base pointers
    const float* wp = s_probs + (size_t)b * KK + k;   // + step*BB*KK
    const float* rp = g_rws + b;                      // + step*BB
    const float* np = noise + (size_t)b * DD + t;     // + step*BB*DD (only t<32)
    float*       yp = ys    + (size_t)b * DD + t;     // + step*BB*DD (only t<32)

    // prefetch step 0
    float w_c = wp[0];
    float r_c = rp[0];
    float dw_c = 0.0f;
    if (t < DD) dw_c = SQDT_F * np[0];

    __syncthreads();

    for (int step = 0; step < TT; step++) {
        // ---- prefetch step+1 (clamped; last-iter value unused) ----
        int tn = step + 1;
        if (tn >= TT) tn = TT - 1;
        float w_n = wp[(size_t)tn * (BB * KK)];
        float r_n = rp[(size_t)tn * BB];
        float dw_n = 0.0f;
        if (t < DD) dw_n = SQDT_F * np[(size_t)tn * (BB * DD)];

        // ---- dot products: acc = A_k[row] . z   (f32x2) ----
        unsigned long long a0a = 0ull, a0b = 0ull, a1a = 0ull, a1b = 0ull;
        const ulonglong2* zv = (const ulonglong2*)(&zbuf[step & 1][0]);
#pragma unroll
        for (int jj = 0; jj < 8; jj++) {
            ulonglong2 z2 = zv[jj];                    // LDS.128 broadcast
            ffma2(a0a, A0[2 * jj],     z2.x);
            ffma2(a0b, A0[2 * jj + 1], z2.y);
            ffma2(a1a, A1[2 * jj],     z2.x);
            ffma2(a1b, A1[2 * jj + 1], z2.y);
        }
        float acc0 = hsum2(add2(a0a, a0b));
        float acc1 = hsum2(add2(a1a, a1b));

        // ---- per-(k,i) partials: pd = wn*(dt*acc + dt*bias), pq = wn*Q ----
        float wn  = w_c * r_c;
        float pd0 = wn * fmaf(DT_F, acc0, dtb0);
        float pd1 = wn * fmaf(DT_F, acc1, dtb1);
        float pq0 = wn * qc0;
        float pq1 = wn * qc1;
        pbuf[i0][k] = make_float2(pd0, pq0);           // STS.64, conflict-free
        pbuf[i1][k] = make_float2(pd1, pq1);

        __syncthreads();

        // ---- phase B: warp 0 reduces over k and updates z ----
        if (t < DD) {
            const ulonglong2* pv = (const ulonglong2*)(&pbuf[t][0]);
            ulonglong2 x0 = pv[0];
            ulonglong2 x1 = pv[1];
            ulonglong2 x2 = pv[2];
            ulonglong2 x3 = pv[3];
            unsigned long long s0 = add2(x0.x, x0.y);
            unsigned long long s1 = add2(x1.x, x1.y);
            unsigned long long s2 = add2(x2.x, x2.y);
            unsigned long long s3 = add2(x3.x, x3.y);
            unsigned long long s  = add2(add2(s0, s1), add2(s2, s3));
            float sumd, sumq;
            unpack2(s, sumd, sumq);
            zreg = fmaf(sumq, dw_c, zreg + sumd);      // z += dt*drift + diff*dw
            zbuf[(step & 1) ^ 1][t] = zreg;
            yp[(size_t)step * (BB * DD)] = zreg;       // coalesced 128B store
        }

        __syncthreads();

        // rotate prefetch
        w_c = w_n;
        r_c = r_n;
        dw_c = dw_n;
    }
}

extern "C" void kernel_launch(void* const* d_in, const int* in_sizes, int n_in,
                              void* d_out, int out_size) {
    const float* z0      = (const float*)d_in[0];
    const float* s_probs = (const float*)d_in[1];
    const float* noise   = (const float*)d_in[2];
    const float* A_s     = (const float*)d_in[3];
    const float* b_s     = (const float*)d_in[4];
    const float* Q_chol  = (const float*)d_in[5];
    float*       ys      = (float*)d_out;

    rws_kernel<<<(TT * BB + 255) / 256, 256>>>(s_probs);
    sde_main<<<BB, 128>>>(z0, s_probs, noise, A_s, b_s, Q_chol, ys);
}

// round 2
// speedup vs baseline: 1.1670x; 1.1670x over previous
#include <cuda_runtime.h>
#include <cstdint>

#define TT 2048
#define BB 512
#define KK 8
#define DD 32
#define DT_F 0.05f
#define SQDT_F 0.22360679774997896f  /* sqrt(0.05) */
#define UN 4                          /* prefetch group / unroll */

// Scratch: normalized weights wn[t][b][k] = s_probs / sum_k. Static (no allocs).
__device__ float g_wn[TT * BB * KK];

// ---------- f32x2 helpers (FFMA2 is PTX-only on sm_103a) ----------
__device__ __forceinline__ unsigned long long add2(unsigned long long a, unsigned long long b) {
    unsigned long long d;
    asm("add.rn.f32x2 %0, %1, %2;" : "=l"(d) : "l"(a), "l"(b));
    return d;
}
__device__ __forceinline__ void ffma2(unsigned long long& d, unsigned long long a, unsigned long long b) {
    asm("fma.rn.f32x2 %0, %1, %2, %3;" : "=l"(d) : "l"(a), "l"(b), "l"(d));
}
__device__ __forceinline__ float hsum2(unsigned long long v) {
    float lo, hi;
    asm("mov.b64 {%0, %1}, %2;" : "=f"(lo), "=f"(hi) : "l"(v));
    return lo + hi;
}

// ---------- Kernel 1: normalized weights ----------
__global__ void __launch_bounds__(256) norm_kernel(const float* __restrict__ s_probs) {
    int idx = blockIdx.x * blockDim.x + threadIdx.x;  // (t,b) pair
    if (idx < TT * BB) {
        const float4* p = (const float4*)(s_probs + (size_t)idx * KK);
        float4 a = p[0];
        float4 b = p[1];
        float s = ((a.x + a.y) + (a.z + a.w)) + ((b.x + b.y) + (b.z + b.w));
        float r = 1.0f / s;
        float4* o = (float4*)(g_wn + (size_t)idx * KK);
        o[0] = make_float4(a.x * r, a.y * r, a.z * r, a.w * r);
        o[1] = make_float4(b.x * r, b.y * r, b.z * r, b.w * r);
    }
}

// ---------- Kernel 2: sequential Euler-Maruyama, one CTA (128 thr) per batch ----------
// Thread t: k = t&7, ih = t>>3 (0..15). Owns A_k rows i0=ih and i1=ih+16 in regs.
// Within each warp, lanes cover all 8 k for 4 consecutive ih values, so the
// k-reduction is an intra-warp 8-lane butterfly. One __syncthreads per step.
__global__ void __launch_bounds__(128, 4) sde_main(
    const float* __restrict__ z0,
    const float* __restrict__ noise,
    const float* __restrict__ A_s,
    const float* __restrict__ b_s,
    const float* __restrict__ Q_chol,
    float* __restrict__ ys)
{
    const int b  = blockIdx.x;
    const int t  = threadIdx.x;
    const int l  = t & 31;
    const int k  = t & 7;
    const int ih = t >> 3;        // 0..15
    const int i0 = ih;
    const int i1 = ih + 16;
    const bool owner = ((l & 7) == 0);

    __shared__ __align__(16) float zbuf[2][DD];

    // ---- A rows -> registers as f32x2 pairs ----
    unsigned long long A0[16], A1[16];
    {
        const ulonglong2* r0 = (const ulonglong2*)(A_s + (size_t)(k * DD + i0) * DD);
        const ulonglong2* r1 = (const ulonglong2*)(A_s + (size_t)(k * DD + i1) * DD);
#pragma unroll
        for (int q = 0; q < 8; q++) {
            ulonglong2 v0 = r0[q]; A0[2 * q] = v0.x; A0[2 * q + 1] = v0.y;
            ulonglong2 v1 = r1[q]; A1[2 * q] = v1.x; A1[2 * q + 1] = v1.y;
        }
    }
    const float dtb0 = DT_F * b_s[k * DD + i0];
    const float dtb1 = DT_F * b_s[k * DD + i1];
    const float qc0  = Q_chol[k * DD + i0];
    const float qc1  = Q_chol[k * DD + i1];

    // ---- z init: every thread keeps (redundant) copies of its two dims ----
    float zreg0 = z0[(size_t)b * DD + i0];
    float zreg1 = z0[(size_t)b * DD + i1];
    if (t < DD) zbuf[0][t] = z0[(size_t)b * DD + t];

    // stream pointers
    const float* wnp = g_wn  + (size_t)b * KK + k;    // + step*BB*KK
    const float* np0 = noise + (size_t)b * DD + i0;   // + step*BB*DD
    const float* np1 = noise + (size_t)b * DD + i1;
    float*       yp0 = ys    + (size_t)b * DD + i0;
    float*       yp1 = ys    + (size_t)b * DD + i1;

    // ---- prefetch group 0 ----
    float wn_c[UN], dw0_c[UN], dw1_c[UN];
#pragma unroll
    for (int u = 0; u < UN; u++) {
        wn_c[u]  = wnp[(size_t)u * (BB * KK)];
        dw0_c[u] = np0[(size_t)u * (BB * DD)];
        dw1_c[u] = np1[(size_t)u * (BB * DD)];
    }

    __syncthreads();

    for (int s0 = 0; s0 < TT; s0 += UN) {
        // ---- prefetch next group (clamped; last-group values unused) ----
        float wn_n[UN], dw0_n[UN], dw1_n[UN];
#pragma unroll
        for (int u = 0; u < UN; u++) {
            int ts = s0 + UN + u;
            if (ts >= TT) ts = TT - 1;
            wn_n[u]  = wnp[(size_t)ts * (BB * KK)];
            dw0_n[u] = np0[(size_t)ts * (BB * DD)];
            dw1_n[u] = np1[(size_t)ts * (BB * DD)];
        }

#pragma unroll
        for (int u = 0; u < UN; u++) {
            const int step = s0 + u;
            const int p = step & 1;

            // ---- dots: acc = A_k[row] . z (f32x2, LDS.128 broadcast) ----
            unsigned long long a0a = 0ull, a0b = 0ull, a1a = 0ull, a1b = 0ull;
            const ulonglong2* zv = (const ulonglong2*)(&zbuf[p][0]);
#pragma unroll
            for (int jj = 0; jj < 8; jj++) {
                ulonglong2 z2 = zv[jj];
                ffma2(a0a, A0[2 * jj],     z2.x);
                ffma2(a0b, A0[2 * jj + 1], z2.y);
                ffma2(a1a, A1[2 * jj],     z2.x);
                ffma2(a1b, A1[2 * jj + 1], z2.y);
            }
            float acc0 = hsum2(add2(a0a, a0b));
            float acc1 = hsum2(add2(a1a, a1b));

            // ---- per-(k,i) weighted partials ----
            float wn = wn_c[u];
            float pd0 = wn * fmaf(DT_F, acc0, dtb0);
            float pd1 = wn * fmaf(DT_F, acc1, dtb1);
            float pq0 = wn * qc0;
            float pq1 = wn * qc1;

            // ---- intra-warp k-reduction (8-lane butterfly) ----
#pragma unroll
            for (int off = 1; off < 8; off <<= 1) {
                pd0 += __shfl_xor_sync(0xFFFFFFFFu, pd0, off);
                pq0 += __shfl_xor_sync(0xFFFFFFFFu, pq0, off);
                pd1 += __shfl_xor_sync(0xFFFFFFFFu, pd1, off);
                pq1 += __shfl_xor_sync(0xFFFFFFFFu, pq1, off);
            }

            // ---- z update (all lanes redundantly; owner publishes) ----
            zreg0 = fmaf(pq0 * SQDT_F, dw0_c[u], zreg0 + pd0);
            zreg1 = fmaf(pq1 * SQDT_F, dw1_c[u], zreg1 + pd1);
            if (owner) {
                zbuf[p ^ 1][i0] = zreg0;
                zbuf[p ^ 1][i1] = zreg1;
                yp0[(size_t)step * (BB * DD)] = zreg0;
                yp1[(size_t)step * (BB * DD)] = zreg1;
            }
            __syncthreads();
        }

        // rotate prefetch buffers
#pragma unroll
        for (int u = 0; u < UN; u++) {
            wn_c[u]  = wn_n[u];
            dw0_c[u] = dw0_n[u];
            dw1_c[u] = dw1_n[u];
        }
    }
}

extern "C" void kernel_launch(void* const* d_in, const int* in_sizes, int n_in,
                              void* d_out, int out_size) {
    const float* z0      = (const float*)d_in[0];
    const float* s_probs = (const float*)d_in[1];
    const float* noise   = (const float*)d_in[2];
    const float* A_s     = (const float*)d_in[3];
    const float* b_s     = (const float*)d_in[4];
    const float* Q_chol  = (const float*)d_in[5];
    float*       ys      = (float*)d_out;

    norm_kernel<<<(TT * BB + 255) / 256, 256>>>(s_probs);
    sde_main<<<BB, 128>>>(z0, noise, A_s, b_s, Q_chol, ys);
}

// round 3
// speedup vs baseline: 1.3326x; 1.1419x over previous
#include <cuda_runtime.h>
#include <cstdint>

#define TT 2048
#define BB 512
#define KK 8
#define DD 32
#define DT_F 0.05f
#define SQDT_F 0.22360679774997896f  /* sqrt(0.05) */
#define UN 4                          /* prefetch group / unroll */

// Scratch: normalized weights wn[t][b][k] = s_probs / sum_k. Static (no allocs).
__device__ float g_wn[TT * BB * KK];

// ---------- f32x2 helpers (FFMA2 is PTX-only on sm_103a) ----------
__device__ __forceinline__ unsigned long long add2(unsigned long long a, unsigned long long b) {
    unsigned long long d;
    asm("add.rn.f32x2 %0, %1, %2;" : "=l"(d) : "l"(a), "l"(b));
    return d;
}
__device__ __forceinline__ void ffma2(unsigned long long& d, unsigned long long a, unsigned long long b) {
    asm("fma.rn.f32x2 %0, %1, %2, %3;" : "=l"(d) : "l"(a), "l"(b), "l"(d));
}
__device__ __forceinline__ float hsum2(unsigned long long v) {
    float lo, hi;
    asm("mov.b64 {%0, %1}, %2;" : "=f"(lo), "=f"(hi) : "l"(v));
    return lo + hi;
}

// ---------- Kernel 1: normalized weights ----------
__global__ void __launch_bounds__(256) norm_kernel(const float* __restrict__ s_probs) {
    int idx = blockIdx.x * blockDim.x + threadIdx.x;  // (t,b) pair
    if (idx < TT * BB) {
        const float4* p = (const float4*)(s_probs + (size_t)idx * KK);
        float4 a = p[0];
        float4 b = p[1];
        float s = ((a.x + a.y) + (a.z + a.w)) + ((b.x + b.y) + (b.z + b.w));
        float r = 1.0f / s;
        float4* o = (float4*)(g_wn + (size_t)idx * KK);
        o[0] = make_float4(a.x * r, a.y * r, a.z * r, a.w * r);
        o[1] = make_float4(b.x * r, b.y * r, b.z * r, b.w * r);
    }
}

// ---------- Kernel 2: one CTA (128 thr) per batch ----------
// Thread t: i = t>>2 (row, 0..31), k2 = t&3. Owns row i of A_{k2} and A_{k2+4}
// in registers. Cross-thread k-reduction = 2-level butterfly over 4 lanes.
__global__ void __launch_bounds__(128, 4) sde_main(
    const float* __restrict__ z0,
    const float* __restrict__ noise,
    const float* __restrict__ A_s,
    const float* __restrict__ b_s,
    const float* __restrict__ Q_chol,
    float* __restrict__ ys)
{
    const int b  = blockIdx.x;
    const int t  = threadIdx.x;
    const int k2 = t & 3;          // k low
    const int k4 = k2 + 4;         // k high
    const int i  = t >> 2;         // row 0..31
    const bool owner = (k2 == 0);

    __shared__ __align__(16) float zbuf[2][DD];

    // ---- A rows -> registers as f32x2 pairs ----
    unsigned long long Aa[16], Ab[16];
    {
        const ulonglong2* ra = (const ulonglong2*)(A_s + (size_t)(k2 * DD + i) * DD);
        const ulonglong2* rb = (const ulonglong2*)(A_s + (size_t)(k4 * DD + i) * DD);
#pragma unroll
        for (int q = 0; q < 8; q++) {
            ulonglong2 va = ra[q]; Aa[2 * q] = va.x; Aa[2 * q + 1] = va.y;
            ulonglong2 vb = rb[q]; Ab[2 * q] = vb.x; Ab[2 * q + 1] = vb.y;
        }
    }
    const float dtba = DT_F * b_s[k2 * DD + i];
    const float dtbb = DT_F * b_s[k4 * DD + i];
    const float qca  = Q_chol[k2 * DD + i];
    const float qcb  = Q_chol[k4 * DD + i];

    // ---- z init ----
    float zreg = z0[(size_t)b * DD + i];
    if (t < DD) zbuf[0][t] = z0[(size_t)b * DD + t];

    // stream pointers
    const float* wpa = g_wn  + (size_t)b * KK + k2;   // + step*BB*KK
    const float* wpb = g_wn  + (size_t)b * KK + k4;
    const float* np  = noise + (size_t)b * DD + i;    // + step*BB*DD
    float*       yp  = ys    + (size_t)b * DD + i;

    // ---- prefetch group 0 ----
    float wa_c[UN], wb_c[UN], dw_c[UN];
#pragma unroll
    for (int u = 0; u < UN; u++) {
        wa_c[u] = wpa[(size_t)u * (BB * KK)];
        wb_c[u] = wpb[(size_t)u * (BB * KK)];
        dw_c[u] = SQDT_F * np[(size_t)u * (BB * DD)];
    }

    __syncthreads();

    for (int s0 = 0; s0 < TT; s0 += UN) {
        // ---- prefetch next group (clamped; last-group values unused) ----
        float wa_n[UN], wb_n[UN], dw_n[UN];
#pragma unroll
        for (int u = 0; u < UN; u++) {
            int ts = s0 + UN + u;
            if (ts >= TT) ts = TT - 1;
            wa_n[u] = wpa[(size_t)ts * (BB * KK)];
            wb_n[u] = wpb[(size_t)ts * (BB * KK)];
            dw_n[u] = SQDT_F * np[(size_t)ts * (BB * DD)];
        }

#pragma unroll
        for (int u = 0; u < UN; u++) {
            const int step = s0 + u;
            const int p = step & 1;

            // ---- dots: row i of A_{k2} and A_{k4} against z (f32x2) ----
            unsigned long long c0a = 0ull, c0b = 0ull, c4a = 0ull, c4b = 0ull;
            const ulonglong2* zv = (const ulonglong2*)(&zbuf[p][0]);
#pragma unroll
            for (int jj = 0; jj < 8; jj++) {
                ulonglong2 z2 = zv[jj];                // LDS.128 broadcast
                ffma2(c0a, Aa[2 * jj],     z2.x);
                ffma2(c0b, Aa[2 * jj + 1], z2.y);
                ffma2(c4a, Ab[2 * jj],     z2.x);
                ffma2(c4b, Ab[2 * jj + 1], z2.y);
            }
            float acc0 = hsum2(add2(c0a, c0b));
            float acc4 = hsum2(add2(c4a, c4b));

            // ---- combine this thread's two k's (register math) ----
            float d0 = fmaf(DT_F, acc0, dtba);
            float d4 = fmaf(DT_F, acc4, dtbb);
            float pd = fmaf(wa_c[u], d0, wb_c[u] * d4);
            float pq = fmaf(wa_c[u], qca, wb_c[u] * qcb);

            // ---- 2-level butterfly over the 4 k2-lanes ----
            pd += __shfl_xor_sync(0xFFFFFFFFu, pd, 1);
            pq += __shfl_xor_sync(0xFFFFFFFFu, pq, 1);
            pd += __shfl_xor_sync(0xFFFFFFFFu, pd, 2);
            pq += __shfl_xor_sync(0xFFFFFFFFu, pq, 2);

            // ---- z update (all 4 lanes redundantly; k2==0 publishes) ----
            zreg = fmaf(pq, dw_c[u], zreg + pd);
            if (owner) {
                zbuf[p ^ 1][i] = zreg;
                yp[(size_t)step * (BB * DD)] = zreg;
            }
            __syncthreads();
        }

        // rotate prefetch buffers
#pragma unroll
        for (int u = 0; u < UN; u++) {
            wa_c[u] = wa_n[u];
            wb_c[u] = wb_n[u];
            dw_c[u] = dw_n[u];
        }
    }
}

extern "C" void kernel_launch(void* const* d_in, const int* in_sizes, int n_in,
                              void* d_out, int out_size) {
    const float* z0      = (const float*)d_in[0];
    const float* s_probs = (const float*)d_in[1];
    const float* noise   = (const float*)d_in[2];
    const float* A_s     = (const float*)d_in[3];
    const float* b_s     = (const float*)d_in[4];
    const float* Q_chol  = (const float*)d_in[5];
    float*       ys      = (float*)d_out;

    norm_kernel<<<(TT * BB + 255) / 256, 256>>>(s_probs);
    sde_main<<<BB, 128>>>(z0, noise, A_s, b_s, Q_chol, ys);
}

// round 4
// speedup vs baseline: 1.5433x; 1.1582x over previous
#include <cuda_runtime.h>
#include <cstdint>

#define TT 2048
#define BB 512
#define KK 8
#define DD 32
#define DT_F 0.05f
#define SQDT_F 0.22360679774997896f  /* sqrt(0.05) */
#define UN 4                          /* prefetch group / unroll */

// Scratch: normalized weights wn[t][b][k] = s_probs / sum_k. Static (no allocs).
__device__ float g_wn[TT * BB * KK];

// ---------- f32x2 helpers (FFMA2 is PTX-only on sm_103a) ----------
__device__ __forceinline__ unsigned long long add2(unsigned long long a, unsigned long long b) {
    unsigned long long d;
    asm("add.rn.f32x2 %0, %1, %2;" : "=l"(d) : "l"(a), "l"(b));
    return d;
}
__device__ __forceinline__ void ffma2(unsigned long long& d, unsigned long long a, unsigned long long b) {
    asm("fma.rn.f32x2 %0, %1, %2, %3;" : "=l"(d) : "l"(a), "l"(b), "l"(d));
}
__device__ __forceinline__ float hsum2(unsigned long long v) {
    float lo, hi;
    asm("mov.b64 {%0, %1}, %2;" : "=f"(lo), "=f"(hi) : "l"(v));
    return lo + hi;
}

// ---------- Kernel 1: normalized weights ----------
__global__ void __launch_bounds__(256) norm_kernel(const float* __restrict__ s_probs) {
    int idx = blockIdx.x * blockDim.x + threadIdx.x;  // (t,b) pair
    if (idx < TT * BB) {
        const float4* p = (const float4*)(s_probs + (size_t)idx * KK);
        float4 a = p[0];
        float4 b = p[1];
        float s = ((a.x + a.y) + (a.z + a.w)) + ((b.x + b.y) + (b.z + b.w));
        float r = 1.0f / s;
        float4* o = (float4*)(g_wn + (size_t)idx * KK);
        o[0] = make_float4(a.x * r, a.y * r, a.z * r, a.w * r);
        o[1] = make_float4(b.x * r, b.y * r, b.z * r, b.w * r);
    }
}

// ---------- Kernel 2: one CTA (64 thr = 2 warps) per batch ----------
// Lane i of warp w owns row i of A_{4w+kk}, kk=0..3, in registers (128 regs).
// k-reduction over the warp's 4 k's is register math; cross-warp reduction is
// one float2 smem exchange + 1 barrier. Each warp keeps a private z copy.
__global__ void __launch_bounds__(64, 4) sde_main(
    const float* __restrict__ z0,
    const float* __restrict__ noise,
    const float* __restrict__ A_s,
    const float* __restrict__ b_s,
    const float* __restrict__ Q_chol,
    float* __restrict__ ys)
{
    const int b    = blockIdx.x;
    const int tid  = threadIdx.x;
    const int w    = tid >> 5;       // 0 or 1
    const int lane = tid & 31;       // row i
    const int kb   = w * 4;          // k base

    __shared__ __align__(16) float  zbuf[2][DD];        // [warp][row] private z copies
    __shared__ __align__(16) float2 pbuf[2][2][DD];     // [parity][warp][row] partials

    // ---- A rows -> registers as f32x2 pairs: A[kk] = row `lane` of A_{kb+kk} ----
    unsigned long long A[4][16];
#pragma unroll
    for (int kk = 0; kk < 4; kk++) {
        const ulonglong2* r = (const ulonglong2*)(A_s + (size_t)((kb + kk) * DD + lane) * DD);
#pragma unroll
        for (int q = 0; q < 8; q++) {
            ulonglong2 v = r[q];
            A[kk][2 * q]     = v.x;
            A[kk][2 * q + 1] = v.y;
        }
    }
    float dtb[4], qc[4];
#pragma unroll
    for (int kk = 0; kk < 4; kk++) {
        dtb[kk] = DT_F * b_s[(kb + kk) * DD + lane];
        qc[kk]  = Q_chol[(kb + kk) * DD + lane];
    }

    // ---- z init ----
    float zreg = z0[(size_t)b * DD + lane];
    zbuf[w][lane] = zreg;

    // stream pointers
    const float4* wp4 = (const float4*)g_wn;            // idx = ((t*BB+b)*KK + kb)/4
    const float*  np  = noise + (size_t)b * DD + lane;  // + step*BB*DD
    float*        yp  = ys    + (size_t)b * DD + lane;

    // ---- prefetch group 0 ----
    float4 w4_c[UN]; float dw_c[UN];
#pragma unroll
    for (int u = 0; u < UN; u++) {
        w4_c[u] = __ldg(&wp4[((size_t)u * BB + b) * 2 + w]);
        dw_c[u] = SQDT_F * __ldg(&np[(size_t)u * (BB * DD)]);
    }

    __syncthreads();

    for (int s0 = 0; s0 < TT; s0 += UN) {
        // ---- prefetch next group (clamped; last-group values unused) ----
        float4 w4_n[UN]; float dw_n[UN];
#pragma unroll
        for (int u = 0; u < UN; u++) {
            int ts = s0 + UN + u;
            if (ts >= TT) ts = TT - 1;
            w4_n[u] = __ldg(&wp4[((size_t)ts * BB + b) * 2 + w]);
            dw_n[u] = SQDT_F * __ldg(&np[(size_t)ts * (BB * DD)]);
        }

#pragma unroll
        for (int u = 0; u < UN; u++) {
            const int step = s0 + u;
            const int par  = step & 1;

            // ---- matvec: 4 rows (one per k) against z (8 LDS.128 + 64 FFMA2) ----
            unsigned long long ca[4] = {0ull, 0ull, 0ull, 0ull};
            unsigned long long cb[4] = {0ull, 0ull, 0ull, 0ull};
            const ulonglong2* zv = (const ulonglong2*)(&zbuf[w][0]);
#pragma unroll
            for (int jj = 0; jj < 8; jj++) {
                ulonglong2 z2 = zv[jj];                 // LDS.128 broadcast
#pragma unroll
                for (int kk = 0; kk < 4; kk++) {
                    ffma2(ca[kk], A[kk][2 * jj],     z2.x);
                    ffma2(cb[kk], A[kk][2 * jj + 1], z2.y);
                }
            }
            float a0 = hsum2(add2(ca[0], cb[0]));
            float a1 = hsum2(add2(ca[1], cb[1]));
            float a2 = hsum2(add2(ca[2], cb[2]));
            float a3 = hsum2(add2(ca[3], cb[3]));

            // ---- weighted combine over this warp's 4 k's (register math) ----
            float4 wv = w4_c[u];
            float pd = fmaf(wv.x, fmaf(DT_F, a0, dtb[0]),
                       fmaf(wv.y, fmaf(DT_F, a1, dtb[1]),
                       fmaf(wv.z, fmaf(DT_F, a2, dtb[2]),
                            wv.w * fmaf(DT_F, a3, dtb[3]))));
            float pq = fmaf(wv.x, qc[0],
                       fmaf(wv.y, qc[1],
                       fmaf(wv.z, qc[2], wv.w * qc[3])));

            // ---- cross-warp reduction: one smem exchange + one barrier ----
            pbuf[par][w][lane] = make_float2(pd, pq);
            __syncthreads();
            float2 o = pbuf[par][w ^ 1][lane];
            pd += o.x;
            pq += o.y;

            // ---- z update (both warps redundantly; each publishes own copy) ----
            zreg = fmaf(pq, dw_c[u], zreg + pd);
            zbuf[w][lane] = zreg;
            if (w == 0) yp[(size_t)step * (BB * DD)] = zreg;  // coalesced 128B
            __syncwarp();
        }

        // rotate prefetch buffers
#pragma unroll
        for (int u = 0; u < UN; u++) {
            w4_c[u] = w4_n[u];
            dw_c[u] = dw_n[u];
        }
    }
}

extern "C" void kernel_launch(void* const* d_in, const int* in_sizes, int n_in,
                              void* d_out, int out_size) {
    const float* z0      = (const float*)d_in[0];
    const float* s_probs = (const float*)d_in[1];
    const float* noise   = (const float*)d_in[2];
    const float* A_s     = (const float*)d_in[3];
    const float* b_s     = (const float*)d_in[4];
    const float* Q_chol  = (const float*)d_in[5];
    float*       ys      = (float*)d_out;

    norm_kernel<<<(TT * BB + 255) / 256, 256>>>(s_probs);
    sde_main<<<BB, 64>>>(z0, noise, A_s, b_s, Q_chol, ys);
}